// round 17
// baseline (speedup 1.0000x reference)
#include <cuda_runtime.h>
#include <cuda_fp16.h>
#include <math.h>

// ---------------------------------------------------------------------------
//   x,y: [64,128,64], HEADS=2, HS=64, LEAKY=0.3
//   fused set_norm+QKV (tf32 TC) -> fused attention+projection ->
//   multi-b fp16-TC cross score (X amortized, Y double-buffered cp.async)
// ---------------------------------------------------------------------------

#define NSET   64
#define NITEM  128
#define DFEAT  64
#define ROWS_ONE (NSET * NITEM)        // 8192
#define ROWS_ALL (2 * ROWS_ONE)        // 16384

__device__ float g_Q   [ROWS_ALL * 128];
__device__ float g_K   [ROWS_ALL * 128];
__device__ float g_V   [ROWS_ALL * 128];
__device__ float g_wf  [128 * 128];                 // Wh @ Wc (fp32)
__device__ __half g_wfT[128 * 128];                 // (Wh@Wc)^T in fp16: [n][k]
__device__ __half g_ph [ROWS_ALL * 128];            // P in fp16

__device__ __forceinline__ unsigned f2tf32(float x) {
    unsigned r;
    asm("cvt.rna.tf32.f32 %0, %1;" : "=r"(r) : "f"(x));
    return r;
}
__device__ __forceinline__ unsigned u2tf32(unsigned u) {
    unsigned r;
    asm("cvt.rna.tf32.f32 %0, %1;" : "=r"(r) : "f"(__uint_as_float(u)));
    return r;
}
__device__ __forceinline__ unsigned smem_u32(const void* p) {
    return (unsigned)__cvta_generic_to_shared(p);
}
__device__ __forceinline__ unsigned pack_h16(float a, float b) {
    __half2 t = __floats2half2_rn(a, b);
    return *(unsigned*)&t;
}
#define CP_ASYNC16(dst_u32, src_ptr) \
    asm volatile("cp.async.cg.shared.global [%0], [%1], 16;" \
                 :: "r"(dst_u32), "l"(src_ptr))
#define CP_COMMIT() asm volatile("cp.async.commit_group;")
#define CP_WAIT0()  asm volatile("cp.async.wait_group 0;")

// ---------------------------------------------------------------------------
// Kernel 2a: small fp32 SGEMM for Wf = Wh @ Wc; also emits WfT in fp16.
// ---------------------------------------------------------------------------
__global__ __launch_bounds__(256) void sgemm_wf_kernel(
    const float* __restrict__ A, const float* __restrict__ B,
    float* __restrict__ C, __half* __restrict__ CT, int M, int N, int K)
{
    __shared__ float As[16][65];
    __shared__ float Bs[16][65];
    const int bx = blockIdx.x, by = blockIdx.y;
    const int tid = threadIdx.x;
    const int tx = tid & 15, ty = tid >> 4;

    float acc[4][4] = {};
    for (int k0 = 0; k0 < K; k0 += 16) {
        #pragma unroll
        for (int i = tid; i < 64 * 16; i += 256) {
            int r = i >> 4, kk = i & 15;
            As[kk][r] = A[(by * 64 + r) * K + k0 + kk];
        }
        #pragma unroll
        for (int i = tid; i < 16 * 64; i += 256) {
            int kk = i >> 6, c = i & 63;
            Bs[kk][c] = B[(k0 + kk) * N + bx * 64 + c];
        }
        __syncthreads();
        #pragma unroll
        for (int kk = 0; kk < 16; kk++) {
            float a[4], b[4];
            #pragma unroll
            for (int i = 0; i < 4; i++) a[i] = As[kk][ty * 4 + i];
            #pragma unroll
            for (int j = 0; j < 4; j++) b[j] = Bs[kk][tx * 4 + j];
            #pragma unroll
            for (int i = 0; i < 4; i++)
                #pragma unroll
                for (int j = 0; j < 4; j++)
                    acc[i][j] = fmaf(a[i], b[j], acc[i][j]);
        }
        __syncthreads();
    }
    #pragma unroll
    for (int i = 0; i < 4; i++)
        #pragma unroll
        for (int j = 0; j < 4; j++) {
            int row = by * 64 + ty * 4 + i, col = bx * 64 + tx * 4 + j;
            C[row * N + col] = acc[i][j];
            CT[col * 128 + row] = __float2half(acc[i][j]);
        }
}

// ---------------------------------------------------------------------------
// Kernel 1+2b FUSED: set-norm + QKV projection. One block per set (128 rows).
// ---------------------------------------------------------------------------
#define QAP 68
#define WP  132
#define SNQKV_SMEM ((128 * QAP + 2 * 64 * WP) * 4)   // 102400 B

__global__ __launch_bounds__(256) void snqkv_kernel(
    const float* __restrict__ X, const float* __restrict__ Y,
    const int* __restrict__ xsz, const int* __restrict__ ysz,
    const float* __restrict__ Wq, const float* __restrict__ Wk,
    const float* __restrict__ Wv,
    float* __restrict__ Q, float* __restrict__ Ko, float* __restrict__ V)
{
    extern __shared__ unsigned smu[];
    unsigned* As  = smu;                     // [128][QAP]
    unsigned* Ws0 = smu + 128 * QAP;         // [64][WP] double buffer
    unsigned* Ws1 = Ws0 + 64 * WP;
    float* Asf = (float*)As;

    __shared__ float rmask[NITEM];
    __shared__ float red[256];
    __shared__ float s_mean, s_inv;

    const int n   = blockIdx.x;
    const int tid = threadIdx.x, lane = tid & 31, w = tid >> 5;
    const int gi = lane >> 2, ti = lane & 3;
    const int r0 = (w & 3) * 32, c0 = (w >> 2) * 64;
    const int rbase = n * NITEM;

    const float* xb = (n < NSET) ? (X + (size_t)n * NITEM * DFEAT)
                                 : (Y + (size_t)(n - NSET) * NITEM * DFEAT);
    const int   szv = (n < NSET) ? xsz[n] : ysz[n - NSET];

    for (int idx = tid; idx < 128 * 16; idx += 256) {
        int row = idx >> 4, c4 = (idx & 15) << 2;
        CP_ASYNC16(smem_u32(As + row * QAP + c4), xb + row * 64 + c4);
    }
    for (int idx = tid; idx < 64 * 32; idx += 256) {
        int k = idx >> 5, c4 = (idx & 31) << 2;
        CP_ASYNC16(smem_u32(Ws0 + k * WP + c4), Wq + k * 128 + c4);
    }
    CP_COMMIT();
    CP_WAIT0();
    __syncthreads();

    if (tid < NITEM) {
        float s = 0.f;
        #pragma unroll
        for (int e = 0; e < DFEAT; e++) s += Asf[tid * QAP + e];
        rmask[tid] = (s != 0.0f) ? 1.0f : 0.0f;
    }

    float tot = 0.f;
    for (int idx = tid; idx < NITEM * DFEAT; idx += 256)
        tot += Asf[(idx >> 6) * QAP + (idx & 63)];
    red[tid] = tot; __syncthreads();
    for (int s = 128; s > 0; s >>= 1) {
        if (tid < s) red[tid] += red[tid + s];
        __syncthreads();
    }
    const float denom = (float)szv * (float)DFEAT;
    if (tid == 0) s_mean = red[0] / denom;
    __syncthreads();
    const float mean = s_mean;

    float ss = 0.f;
    for (int idx = tid; idx < NITEM * DFEAT; idx += 256) {
        float d = Asf[(idx >> 6) * QAP + (idx & 63)] - mean;
        ss += d * d * rmask[idx >> 6];
    }
    __syncthreads();
    red[tid] = ss; __syncthreads();
    for (int s = 128; s > 0; s >>= 1) {
        if (tid < s) red[tid] += red[tid + s];
        __syncthreads();
    }
    if (tid == 0) s_inv = 1.0f / (sqrtf(red[0] / denom) + 1e-8f);
    __syncthreads();
    const float inv = s_inv;

    for (int idx = tid; idx < NITEM * DFEAT; idx += 256) {
        int row = idx >> 6, e = idx & 63;
        Asf[row * QAP + e] = (Asf[row * QAP + e] - mean) * inv * rmask[row];
    }
    __syncthreads();

    const float* Warr[3] = {Wq, Wk, Wv};
    float*       Carr[3] = {Q, Ko, V};

    #pragma unroll
    for (int sel = 0; sel < 3; sel++) {
        unsigned* Wcur = (sel & 1) ? Ws1 : Ws0;
        unsigned* Wnxt = (sel & 1) ? Ws0 : Ws1;
        if (sel < 2) {
            const float* Wn = Warr[sel + 1];
            for (int idx = tid; idx < 64 * 32; idx += 256) {
                int k = idx >> 5, c4 = (idx & 31) << 2;
                CP_ASYNC16(smem_u32(Wnxt + k * WP + c4), Wn + k * 128 + c4);
            }
            CP_COMMIT();
        }

        float acc[64];
        #pragma unroll
        for (int i = 0; i < 64; i++) acc[i] = 0.f;

        #pragma unroll
        for (int k0 = 0; k0 < 64; k0 += 8) {
            unsigned af[2][4];
            #pragma unroll
            for (int m = 0; m < 2; m++) {
                const unsigned* ab = As + (r0 + m * 16 + gi) * QAP + k0 + ti;
                af[m][0] = u2tf32(ab[0]);
                af[m][1] = u2tf32(ab[8 * QAP]);
                af[m][2] = u2tf32(ab[4]);
                af[m][3] = u2tf32(ab[8 * QAP + 4]);
            }
            #pragma unroll
            for (int nf = 0; nf < 8; nf++) {
                const unsigned* bb = Wcur + (k0 + ti) * WP + c0 + nf * 8 + gi;
                unsigned b0 = u2tf32(bb[0]);
                unsigned b1 = u2tf32(bb[4 * WP]);
                #pragma unroll
                for (int m = 0; m < 2; m++) {
                    float* c = &acc[(m * 8 + nf) * 4];
                    asm volatile(
                        "mma.sync.aligned.m16n8k8.row.col.f32.tf32.tf32.f32 "
                        "{%0,%1,%2,%3}, {%4,%5,%6,%7}, {%8,%9}, {%0,%1,%2,%3};"
                        : "+f"(c[0]), "+f"(c[1]), "+f"(c[2]), "+f"(c[3])
                        : "r"(af[m][0]), "r"(af[m][1]), "r"(af[m][2]), "r"(af[m][3]),
                          "r"(b0), "r"(b1));
                }
            }
        }

        float* C = Carr[sel];
        #pragma unroll
        for (int m = 0; m < 2; m++)
            #pragma unroll
            for (int nf = 0; nf < 8; nf++) {
                const float* c = &acc[(m * 8 + nf) * 4];
                int row = rbase + r0 + m * 16 + gi;
                int col = c0 + nf * 8 + 2 * ti;
                *(float2*)(C + row * 128 + col)       = make_float2(c[0], c[1]);
                *(float2*)(C + (row + 8) * 128 + col) = make_float2(c[2], c[3]);
            }

        CP_WAIT0();
        __syncthreads();
    }
}

// ---------------------------------------------------------------------------
// Kernel 3 FUSED: attention + projection. One block (256 thr) per SET.
// ---------------------------------------------------------------------------
#define AP 132
#define HP 68
#define VPW 68
#define ATTN_SMEM ((2 * 128 * AP + 128 * VPW) * 4)   // 169984 B

__global__ __launch_bounds__(256) void attnproj_kernel(
    const float* __restrict__ Q, const float* __restrict__ K,
    const float* __restrict__ V, const __half* __restrict__ WfT,
    __half* __restrict__ P)
{
    extern __shared__ unsigned smu[];
    unsigned* Qs = smu;                      // [128][AP] tf32 (later att fp16 [128][HP])
    unsigned* Ks = smu + 128 * AP;           // [128][AP] tf32 (later WfT fp16 [128][HP])
    unsigned* Vs = smu + 2 * 128 * AP;       // [128][VPW] half2 words

    const int g = blockIdx.x;
    const int tid = threadIdx.x, lane = tid & 31, w = tid >> 5;
    const int gi = lane >> 2, ti = lane & 3;
    const int hsel = w >> 2, wi = w & 3;
    const int r0 = wi * 32;
    const int hc = hsel * 64;
    const int rowbase = g * NITEM;

    for (int idx = tid; idx < 128 * 32; idx += 256) {
        int row = idx >> 5, c4 = (idx & 31) << 2;
        float4 qv = *(const float4*)&Q[(rowbase + row) * 128 + c4];
        float4 kv = *(const float4*)&K[(rowbase + row) * 128 + c4];
        unsigned* qd = Qs + row * AP + c4;
        unsigned* kd = Ks + row * AP + c4;
        qd[0] = f2tf32(qv.x); qd[1] = f2tf32(qv.y);
        qd[2] = f2tf32(qv.z); qd[3] = f2tf32(qv.w);
        kd[0] = f2tf32(kv.x); kd[1] = f2tf32(kv.y);
        kd[2] = f2tf32(kv.z); kd[3] = f2tf32(kv.w);
    }
    for (int idx = tid; idx < 128 * 64; idx += 256) {
        int row = idx >> 6, c = idx & 63;
        float2 vv = *(const float2*)&V[(rowbase + row) * 128 + 2 * c];
        Vs[row * VPW + c] = pack_h16(vv.x, vv.y);
    }
    __syncthreads();

    float sacc[2][16][4];
    #pragma unroll
    for (int m = 0; m < 2; m++)
        #pragma unroll
        for (int nf = 0; nf < 16; nf++)
            #pragma unroll
            for (int r = 0; r < 4; r++) sacc[m][nf][r] = 0.f;

    #pragma unroll
    for (int k0 = 0; k0 < 64; k0 += 8) {
        unsigned af[2][4];
        #pragma unroll
        for (int m = 0; m < 2; m++) {
            const unsigned* ab = Qs + (r0 + m * 16 + gi) * AP + hc + k0 + ti;
            af[m][0] = ab[0];
            af[m][1] = ab[8 * AP];
            af[m][2] = ab[4];
            af[m][3] = ab[8 * AP + 4];
        }
        #pragma unroll
        for (int nf = 0; nf < 16; nf++) {
            const unsigned* bb = Ks + (nf * 8 + gi) * AP + hc + k0 + ti;
            unsigned b0 = bb[0], b1 = bb[4];
            #pragma unroll
            for (int m = 0; m < 2; m++) {
                float* c = sacc[m][nf];
                asm volatile(
                    "mma.sync.aligned.m16n8k8.row.col.f32.tf32.tf32.f32 "
                    "{%0,%1,%2,%3}, {%4,%5,%6,%7}, {%8,%9}, {%0,%1,%2,%3};"
                    : "+f"(c[0]), "+f"(c[1]), "+f"(c[2]), "+f"(c[3])
                    : "r"(af[m][0]), "r"(af[m][1]), "r"(af[m][2]), "r"(af[m][3]),
                      "r"(b0), "r"(b1));
            }
        }
    }

    __syncthreads();
    for (int idx = tid; idx < 128 * 16; idx += 256) {
        int nrow = idx >> 4, w4 = (idx & 15) << 2;
        CP_ASYNC16(smem_u32(Ks + nrow * HP + w4), WfT + nrow * 128 + (w4 << 1));
    }
    CP_COMMIT();

    const float COEF = 0.125f * 1.44269504f;
    float invd0[2], invd1[2];
    unsigned pf[2][8][4];

    #pragma unroll
    for (int mf = 0; mf < 2; mf++) {
        float mx0 = -3.4e38f, mx1 = -3.4e38f;
        #pragma unroll
        for (int nf = 0; nf < 16; nf++) {
            mx0 = fmaxf(mx0, fmaxf(sacc[mf][nf][0], sacc[mf][nf][1]));
            mx1 = fmaxf(mx1, fmaxf(sacc[mf][nf][2], sacc[mf][nf][3]));
        }
        #pragma unroll
        for (int o = 1; o < 4; o <<= 1) {
            mx0 = fmaxf(mx0, __shfl_xor_sync(0xffffffffu, mx0, o));
            mx1 = fmaxf(mx1, __shfl_xor_sync(0xffffffffu, mx1, o));
        }
        float d0 = 0.f, d1 = 0.f;
        #pragma unroll
        for (int nf = 0; nf < 16; nf++) {
            float raw0 = sacc[mf][nf][0], raw1 = sacc[mf][nf][1];
            float raw2 = sacc[mf][nf][2], raw3 = sacc[mf][nf][3];
            float p0 = (raw0 != 0.f) ? exp2f((raw0 - mx0) * COEF) : 0.f;
            float p1 = (raw1 != 0.f) ? exp2f((raw1 - mx0) * COEF) : 0.f;
            float p2 = (raw2 != 0.f) ? exp2f((raw2 - mx1) * COEF) : 0.f;
            float p3 = (raw3 != 0.f) ? exp2f((raw3 - mx1) * COEF) : 0.f;
            sacc[mf][nf][0] = p0; sacc[mf][nf][1] = p1;
            sacc[mf][nf][2] = p2; sacc[mf][nf][3] = p3;
            d0 += p0 + p1; d1 += p2 + p3;
        }
        #pragma unroll
        for (int o = 1; o < 4; o <<= 1) {
            d0 += __shfl_xor_sync(0xffffffffu, d0, o);
            d1 += __shfl_xor_sync(0xffffffffu, d1, o);
        }
        invd0[mf] = 1.0f / (d0 + 1e-10f);
        invd1[mf] = 1.0f / (d1 + 1e-10f);

        #pragma unroll
        for (int fp = 0; fp < 8; fp++) {
            pf[mf][fp][0] = pack_h16(sacc[mf][2 * fp][0],     sacc[mf][2 * fp][1]);
            pf[mf][fp][1] = pack_h16(sacc[mf][2 * fp][2],     sacc[mf][2 * fp][3]);
            pf[mf][fp][2] = pack_h16(sacc[mf][2 * fp + 1][0], sacc[mf][2 * fp + 1][1]);
            pf[mf][fp][3] = pack_h16(sacc[mf][2 * fp + 1][2], sacc[mf][2 * fp + 1][3]);
        }
    }

    float oacc[2][8][4];
    #pragma unroll
    for (int m = 0; m < 2; m++)
        #pragma unroll
        for (int nf = 0; nf < 8; nf++)
            #pragma unroll
            for (int r = 0; r < 4; r++) oacc[m][nf][r] = 0.f;

    const unsigned vbase = smem_u32(Vs);
    #pragma unroll
    for (int kb = 0; kb < 8; kb++) {
        unsigned bfr[8][2];
        #pragma unroll
        for (int ng = 0; ng < 4; ng++) {
            unsigned t0, t1, t2, t3;
            unsigned addr = vbase +
                ((kb * 16 + (lane & 15)) * VPW + hsel * 32 + ng * 8 + (lane >> 4) * 4) * 4;
            asm volatile(
                "ldmatrix.sync.aligned.m8n8.x4.trans.shared.b16 {%0,%1,%2,%3}, [%4];"
                : "=r"(t0), "=r"(t1), "=r"(t2), "=r"(t3) : "r"(addr));
            bfr[2 * ng][0]     = t0; bfr[2 * ng][1]     = t1;
            bfr[2 * ng + 1][0] = t2; bfr[2 * ng + 1][1] = t3;
        }
        #pragma unroll
        for (int nf = 0; nf < 8; nf++)
            #pragma unroll
            for (int m = 0; m < 2; m++) {
                float* c = oacc[m][nf];
                asm volatile(
                    "mma.sync.aligned.m16n8k16.row.col.f32.f16.f16.f32 "
                    "{%0,%1,%2,%3}, {%4,%5,%6,%7}, {%8,%9}, {%0,%1,%2,%3};"
                    : "+f"(c[0]), "+f"(c[1]), "+f"(c[2]), "+f"(c[3])
                    : "r"(pf[m][kb][0]), "r"(pf[m][kb][1]),
                      "r"(pf[m][kb][2]), "r"(pf[m][kb][3]),
                      "r"(bfr[nf][0]), "r"(bfr[nf][1]));
            }
    }

    CP_WAIT0();
    __syncthreads();
    unsigned* atts = Qs;
    #pragma unroll
    for (int m = 0; m < 2; m++)
        #pragma unroll
        for (int nf = 0; nf < 8; nf++) {
            const float* c = oacc[m][nf];
            int row = r0 + m * 16 + gi;
            int wcol = (hc >> 1) + nf * 4 + ti;
            atts[row * HP + wcol]       = pack_h16(c[0] * invd0[m], c[1] * invd0[m]);
            atts[(row + 8) * HP + wcol] = pack_h16(c[2] * invd1[m], c[3] * invd1[m]);
        }
    __syncthreads();

    const int r0p = (w & 3) * 32, c0p = (w >> 2) * 64;
    const int lrow = lane & 15, lhi = lane >> 4;
    const unsigned abase = smem_u32(atts);
    const unsigned bbase = smem_u32(Ks);

    float acc[64];
    #pragma unroll
    for (int i = 0; i < 64; i++) acc[i] = 0.f;

    #pragma unroll
    for (int ks = 0; ks < 8; ks++) {
        const int kw = ks * 8;
        unsigned af[2][4];
        #pragma unroll
        for (int m = 0; m < 2; m++) {
            unsigned addr = abase + ((r0p + m * 16 + lrow) * HP + kw) * 4 + lhi * 16;
            asm volatile(
                "ldmatrix.sync.aligned.m8n8.x4.shared.b16 {%0,%1,%2,%3}, [%4];"
                : "=r"(af[m][0]), "=r"(af[m][1]), "=r"(af[m][2]), "=r"(af[m][3])
                : "r"(addr));
        }
        unsigned bf[8][2];
        #pragma unroll
        for (int nn = 0; nn < 4; nn++) {
            unsigned t0, t1, t2, t3;
            unsigned addr = bbase + ((c0p + nn * 16 + lrow) * HP + kw) * 4 + lhi * 16;
            asm volatile(
                "ldmatrix.sync.aligned.m8n8.x4.shared.b16 {%0,%1,%2,%3}, [%4];"
                : "=r"(t0), "=r"(t1), "=r"(t2), "=r"(t3)
                : "r"(addr));
            bf[nn * 2][0]     = t0; bf[nn * 2][1]     = t2;
            bf[nn * 2 + 1][0] = t1; bf[nn * 2 + 1][1] = t3;
        }
        #pragma unroll
        for (int n = 0; n < 8; n++)
            #pragma unroll
            for (int m = 0; m < 2; m++) {
                float* c = &acc[m * 32 + n * 4];
                asm volatile(
                    "mma.sync.aligned.m16n8k16.row.col.f32.f16.f16.f32 "
                    "{%0,%1,%2,%3}, {%4,%5,%6,%7}, {%8,%9}, {%0,%1,%2,%3};"
                    : "+f"(c[0]), "+f"(c[1]), "+f"(c[2]), "+f"(c[3])
                    : "r"(af[m][0]), "r"(af[m][1]), "r"(af[m][2]), "r"(af[m][3]),
                      "r"(bf[n][0]), "r"(bf[n][1]));
            }
    }

    #pragma unroll
    for (int m = 0; m < 2; m++)
        #pragma unroll
        for (int n = 0; n < 8; n++) {
            const float* c = &acc[m * 32 + n * 4];
            int row = rowbase + r0p + m * 16 + gi;
            int col = c0p + n * 8 + 2 * ti;
            *(__half2*)(P + row * 128 + col) = __floats2half2_rn(c[0], c[1]);
            *(__half2*)(P + (row + 8) * 128 + col) = __floats2half2_rn(c[2], c[3]);
        }
}

// ---------------------------------------------------------------------------
// Kernel 4: multi-b cross score. grid (16, 64): block = (a, 4 b's).
// X resident; Y double-buffered via cp.async (overlap with compute).
// ---------------------------------------------------------------------------
#define BPW 68
#define CROSS_SMEM (3 * 128 * BPW * 4)       // 104448 B

__global__ __launch_bounds__(256) void cross_mb_kernel(
    const __half* __restrict__ P, const int* __restrict__ xsz,
    const float* __restrict__ Wc2, float* __restrict__ out)
{
    extern __shared__ unsigned smu[];
    unsigned* Xs  = smu;                     // [128][BPW]
    unsigned* Ys0 = smu + 128 * BPW;
    unsigned* Ys1 = Ys0 + 128 * BPW;
    __shared__ float red[16];

    const int bq = blockIdx.x, a = blockIdx.y;
    const int tid  = threadIdx.x;
    const int lane = tid & 31, w = tid >> 5;
    const int r0 = (w & 3) * 32, c0 = (w >> 2) * 64;
    const int lrow = lane & 15;
    const int lhi  = lane >> 4;

    const __half* xp = P + (size_t)a * NITEM * 128;
    const __half* ypb = P + (size_t)ROWS_ONE * 128;

    for (int idx = tid; idx < 128 * 16; idx += 256) {
        int row = idx >> 4, w4 = (idx & 15) << 2;
        CP_ASYNC16(smem_u32(Xs + row * BPW + w4), xp + row * 128 + (w4 << 1));
        CP_ASYNC16(smem_u32(Ys0 + row * BPW + w4),
                   ypb + (size_t)(bq * 4) * NITEM * 128 + row * 128 + (w4 << 1));
    }
    CP_COMMIT();
    CP_WAIT0();
    __syncthreads();

    const unsigned xbase = smem_u32(Xs);
    const float wc0 = Wc2[0], wc1 = Wc2[1];

    #pragma unroll
    for (int j = 0; j < 4; j++) {
        const int b = bq * 4 + j;
        unsigned* Ycur = (j & 1) ? Ys1 : Ys0;
        unsigned* Ynxt = (j & 1) ? Ys0 : Ys1;

        if (j < 3) {
            const __half* yn = ypb + (size_t)(b + 1) * NITEM * 128;
            for (int idx = tid; idx < 128 * 16; idx += 256) {
                int row = idx >> 4, w4 = (idx & 15) << 2;
                CP_ASYNC16(smem_u32(Ynxt + row * BPW + w4),
                           yn + row * 128 + (w4 << 1));
            }
            CP_COMMIT();
        }

        const unsigned ybase = smem_u32(Ycur);
        float hsum[2];
        #pragma unroll
        for (int h = 0; h < 2; h++) {
            const int hw = h * 32;
            float acc[64];
            #pragma unroll
            for (int i = 0; i < 64; i++) acc[i] = 0.f;

            #pragma unroll
            for (int ks = 0; ks < 4; ks++) {
                const int kw = hw + ks * 8;
                unsigned af[2][4];
                #pragma unroll
                for (int m = 0; m < 2; m++) {
                    unsigned addr = xbase +
                        ((r0 + m * 16 + lrow) * BPW + kw) * 4 + lhi * 16;
                    asm volatile(
                        "ldmatrix.sync.aligned.m8n8.x4.shared.b16 {%0,%1,%2,%3}, [%4];"
                        : "=r"(af[m][0]), "=r"(af[m][1]), "=r"(af[m][2]), "=r"(af[m][3])
                        : "r"(addr));
                }
                unsigned bf[8][2];
                #pragma unroll
                for (int nn = 0; nn < 4; nn++) {
                    unsigned t0, t1, t2, t3;
                    unsigned addr = ybase +
                        ((c0 + nn * 16 + lrow) * BPW + kw) * 4 + lhi * 16;
                    asm volatile(
                        "ldmatrix.sync.aligned.m8n8.x4.shared.b16 {%0,%1,%2,%3}, [%4];"
                        : "=r"(t0), "=r"(t1), "=r"(t2), "=r"(t3)
                        : "r"(addr));
                    bf[nn * 2][0]     = t0; bf[nn * 2][1]     = t2;
                    bf[nn * 2 + 1][0] = t1; bf[nn * 2 + 1][1] = t3;
                }
                #pragma unroll
                for (int n = 0; n < 8; n++)
                    #pragma unroll
                    for (int m = 0; m < 2; m++) {
                        float* c = &acc[m * 32 + n * 4];
                        asm volatile(
                            "mma.sync.aligned.m16n8k16.row.col.f32.f16.f16.f32 "
                            "{%0,%1,%2,%3}, {%4,%5,%6,%7}, {%8,%9}, {%0,%1,%2,%3};"
                            : "+f"(c[0]), "+f"(c[1]), "+f"(c[2]), "+f"(c[3])
                            : "r"(af[m][0]), "r"(af[m][1]), "r"(af[m][2]), "r"(af[m][3]),
                              "r"(bf[n][0]), "r"(bf[n][1]));
                    }
            }

            float s = 0.f;
            #pragma unroll
            for (int i = 0; i < 64; i++) {
                float v = acc[i];
                s += (v > 0.f) ? v : 0.3f * v;
            }
            hsum[h] = s;
        }

        float s0 = hsum[0], s1 = hsum[1];
        #pragma unroll
        for (int o = 16; o > 0; o >>= 1) {
            s0 += __shfl_xor_sync(0xffffffffu, s0, o);
            s1 += __shfl_xor_sync(0xffffffffu, s1, o);
        }
        if (lane == 0) { red[w] = s0; red[8 + w] = s1; }
        __syncthreads();
        if (tid == 0) {
            float S0 = 0.f, S1 = 0.f;
            #pragma unroll
            for (int i = 0; i < 8; i++) { S0 += red[i]; S1 += red[8 + i]; }
            float scale = 1.0f / (8.0f * (float)xsz[b] * 128.0f);
            out[a * NSET + b] = (S0 * wc0 + S1 * wc1) * scale;
        }
        CP_WAIT0();
        __syncthreads();
    }
}

// ---------------------------------------------------------------------------
// Launch
// ---------------------------------------------------------------------------
extern "C" void kernel_launch(void* const* d_in, const int* in_sizes, int n_in,
                              void* d_out, int out_size)
{
    const float* x    = (const float*)d_in[0];
    const float* y    = (const float*)d_in[1];
    const float* Wq   = (const float*)d_in[2];
    const float* Wk   = (const float*)d_in[3];
    const float* Wv   = (const float*)d_in[4];
    const float* Wh   = (const float*)d_in[5];
    const float* Wc   = (const float*)d_in[6];
    const float* Wc2  = (const float*)d_in[7];
    const int*   xsz  = (const int*)d_in[8];
    const int*   ysz  = (const int*)d_in[9];
    float* out = (float*)d_out;

    float *pQ, *pK, *pV, *pWf;
    __half *pWfT, *pPh;
    cudaGetSymbolAddress((void**)&pQ,   g_Q);
    cudaGetSymbolAddress((void**)&pK,   g_K);
    cudaGetSymbolAddress((void**)&pV,   g_V);
    cudaGetSymbolAddress((void**)&pWf,  g_wf);
    cudaGetSymbolAddress((void**)&pWfT, g_wfT);
    cudaGetSymbolAddress((void**)&pPh,  g_ph);

    cudaFuncSetAttribute(attnproj_kernel, cudaFuncAttributeMaxDynamicSharedMemorySize, ATTN_SMEM);
    cudaFuncSetAttribute(cross_mb_kernel, cudaFuncAttributeMaxDynamicSharedMemorySize, CROSS_SMEM);
    cudaFuncSetAttribute(snqkv_kernel,    cudaFuncAttributeMaxDynamicSharedMemorySize, SNQKV_SMEM);

    sgemm_wf_kernel<<<dim3(2, 2), 256>>>(Wh, Wc, pWf, pWfT, 128, 128, 64);

    snqkv_kernel<<<2 * NSET, 256, SNQKV_SMEM>>>(
        x, y, xsz, ysz, Wq, Wk, Wv, pQ, pK, pV);

    attnproj_kernel<<<2 * NSET, 256, ATTN_SMEM>>>(pQ, pK, pV, pWfT, pPh);

    cross_mb_kernel<<<dim3(NSET / 4, NSET), 256, CROSS_SMEM>>>(pPh, xsz, Wc2, out);
}